// round 9
// baseline (speedup 1.0000x reference)
#include <cuda_runtime.h>
#include <cuda_bf16.h>
#include <cstdint>

#define NUM_H 16
#define SEQ_T 2048
#define DIM   1024
#define HD    64

// ---------------- scratch (__device__ globals) -----------------------------
__device__ __align__(16) __nv_bfloat16 gA_hi[SEQ_T][DIM];
__device__ __align__(16) __nv_bfloat16 gA_lo[SEQ_T][DIM];
__device__ __align__(16) __nv_bfloat16 gBq_hi[3 * DIM][DIM];   // [N][K]
__device__ __align__(16) __nv_bfloat16 gBq_lo[3 * DIM][DIM];
__device__ __align__(16) __nv_bfloat16 gBp_hi[DIM][DIM];
__device__ __align__(16) __nv_bfloat16 gBp_lo[DIM][DIM];
__device__ __align__(16) __nv_bfloat16 gY_hi[SEQ_T][DIM];
__device__ __align__(16) __nv_bfloat16 gY_lo[SEQ_T][DIM];

// per-head split Q/K/V (Q pre-scaled by 1/8)
__device__ __align__(16) __nv_bfloat16 gQh[NUM_H][SEQ_T][HD];
__device__ __align__(16) __nv_bfloat16 gQl[NUM_H][SEQ_T][HD];
__device__ __align__(16) __nv_bfloat16 gKh[NUM_H][SEQ_T][HD];
__device__ __align__(16) __nv_bfloat16 gKl[NUM_H][SEQ_T][HD];
__device__ __align__(16) __nv_bfloat16 gVh[NUM_H][SEQ_T][HD];
__device__ __align__(16) __nv_bfloat16 gVl[NUM_H][SEQ_T][HD];

// ---------------- PTX helpers ----------------------------------------------
__device__ __forceinline__ uint32_t smem_u32(const void* p) {
    uint32_t a;
    asm("{ .reg .u64 t; cvta.to.shared.u64 t, %1; cvt.u32.u64 %0, t; }" : "=r"(a) : "l"(p));
    return a;
}
#define CP_ASYNC16(dst, src) \
    asm volatile("cp.async.cg.shared.global [%0], [%1], 16;" :: "r"(dst), "l"(src))
#define CP_COMMIT() asm volatile("cp.async.commit_group;" ::: "memory")
#define CP_WAIT(n)  asm volatile("cp.async.wait_group %0;" :: "n"(n) : "memory")

__device__ __forceinline__ void ldsm4(uint32_t* r, uint32_t addr) {
    asm volatile("ldmatrix.sync.aligned.m8n8.x4.shared.b16 {%0,%1,%2,%3}, [%4];"
        : "=r"(r[0]), "=r"(r[1]), "=r"(r[2]), "=r"(r[3]) : "r"(addr));
}
__device__ __forceinline__ void ldsm4t(uint32_t* r, uint32_t addr) {
    asm volatile("ldmatrix.sync.aligned.m8n8.x4.trans.shared.b16 {%0,%1,%2,%3}, [%4];"
        : "=r"(r[0]), "=r"(r[1]), "=r"(r[2]), "=r"(r[3]) : "r"(addr));
}
__device__ __forceinline__ void mma16816(float* d, const uint32_t* a,
                                         uint32_t b0, uint32_t b1) {
    asm volatile("mma.sync.aligned.m16n8k16.row.col.f32.bf16.bf16.f32 "
        "{%0,%1,%2,%3}, {%4,%5,%6,%7}, {%8,%9}, {%0,%1,%2,%3};"
        : "+f"(d[0]), "+f"(d[1]), "+f"(d[2]), "+f"(d[3])
        : "r"(a[0]), "r"(a[1]), "r"(a[2]), "r"(a[3]), "r"(b0), "r"(b1));
}
// split two floats into packed bf16x2 hi and residual lo
__device__ __forceinline__ void split2(float x, float y, uint32_t& hi, uint32_t& lo) {
    __nv_bfloat16 hx = __float2bfloat16(x), hy = __float2bfloat16(y);
    __nv_bfloat16 lx = __float2bfloat16(x - __bfloat162float(hx));
    __nv_bfloat16 ly = __float2bfloat16(y - __bfloat162float(hy));
    __nv_bfloat162 H(hx, hy), L(lx, ly);
    hi = *(uint32_t*)&H;
    lo = *(uint32_t*)&L;
}

// ---------------- convert kernels ------------------------------------------
__global__ void conv_split_kernel(const float* __restrict__ src)
{
    __nv_bfloat16* hi = &gA_hi[0][0];
    __nv_bfloat16* lo = &gA_lo[0][0];
    int i = (blockIdx.x * blockDim.x + threadIdx.x) * 4;
    float4 v = *(const float4*)(src + i);
    uint32_t h01, l01, h23, l23;
    split2(v.x, v.y, h01, l01);
    split2(v.z, v.w, h23, l23);
    *(uint32_t*)(hi + i)     = h01;
    *(uint32_t*)(hi + i + 2) = h23;
    *(uint32_t*)(lo + i)     = l01;
    *(uint32_t*)(lo + i + 2) = l23;
}

template<int MODE>   // W[K][N] -> out[N][K] hi/lo.  0: W_qkv ; 1: W_proj
__global__ void transpose_split_kernel(const float* __restrict__ W)
{
    const int N = (MODE == 0) ? 3 * DIM : DIM;
    __nv_bfloat16* hi = (MODE == 0) ? &gBq_hi[0][0] : &gBp_hi[0][0];
    __nv_bfloat16* lo = (MODE == 0) ? &gBq_lo[0][0] : &gBp_lo[0][0];
    __shared__ float t[32][33];
    const int n0 = blockIdx.x * 32, k0 = blockIdx.y * 32;
    const int tx = threadIdx.x, ty = threadIdx.y;
    #pragma unroll
    for (int i = ty; i < 32; i += 8)
        t[i][tx] = W[(size_t)(k0 + i) * N + n0 + tx];
    __syncthreads();
    #pragma unroll
    for (int i = ty; i < 32; i += 8) {
        float v = t[tx][i];
        __nv_bfloat16 h = __float2bfloat16(v);
        __nv_bfloat16 l = __float2bfloat16(v - __bfloat162float(h));
        hi[(size_t)(n0 + i) * DIM + k0 + tx] = h;
        lo[(size_t)(n0 + i) * DIM + k0 + tx] = l;
    }
}

// ---------------- warp-mma bf16 3-split GEMM -------------------------------
// CTA tile 128x128, 128 threads = 4 warps in 2x2 grid, warp tile 64x64.
// Per k16-step: 16 LDSM feed 96 HMMA (ratio 6) to relieve smem crossbar.
// MODE 0: A=gA,B=gBq -> split bf16 scatter into gQ/gK/gV (q*0.125)
// MODE 1: A=gY,B=gBp -> fp32 C
#define KCHUNK   32
#define RSTRIDE  40
#define TILE_B   (128 * RSTRIDE * 2)
#define STAGE_B  (4 * TILE_B)
#define GEMM_SMEM (2 * STAGE_B)          // 81920 B

template<int MODE>
__global__ __launch_bounds__(128, 2)
void mma_gemm_kernel(float* __restrict__ C, int N)
{
    extern __shared__ char smem[];
    const uint32_t sb = smem_u32(smem);
    const int tid = threadIdx.x;
    const int bm = blockIdx.y, bn = blockIdx.x;
    const int w = tid >> 5, lane = tid & 31;
    const int wm = w >> 1, wn = w & 1;            // 2 x 2 warp grid, 64x64 tiles
    const int lrow = lane & 15, lcol8 = (lane >> 4) * 8;
    const int gid = lane >> 2, tig = lane & 3;

    const __nv_bfloat16* Ahi = (MODE == 0) ? &gA_hi[0][0] : &gY_hi[0][0];
    const __nv_bfloat16* Alo = (MODE == 0) ? &gA_lo[0][0] : &gY_lo[0][0];
    const __nv_bfloat16* Bhi = (MODE == 0) ? &gBq_hi[0][0] : &gBp_hi[0][0];
    const __nv_bfloat16* Blo = (MODE == 0) ? &gBq_lo[0][0] : &gBp_lo[0][0];
    const __nv_bfloat16* srcs[4] = { Ahi, Alo, Bhi, Blo };

    // per-thread copy slots: 16 x (tile, row, seg), 128 threads
    int cp_tile[16], cp_row[16], cp_seg[16];
    #pragma unroll
    for (int it = 0; it < 16; ++it) {
        int idx = it * 128 + tid;
        cp_tile[it] = idx >> 9;
        cp_row[it]  = (idx & 511) >> 2;
        cp_seg[it]  = idx & 3;
    }

    auto issue_load = [&](int c) {
        const uint32_t st = sb + (uint32_t)(c & 1) * STAGE_B;
        const int k0 = c * KCHUNK;
        #pragma unroll
        for (int it = 0; it < 16; ++it) {
            const int t = cp_tile[it];
            const int rbase = ((t < 2) ? bm : bn) * 128;
            const __nv_bfloat16* src = srcs[t]
                + (size_t)(rbase + cp_row[it]) * DIM + k0 + cp_seg[it] * 8;
            const uint32_t dst = st + t * TILE_B + cp_row[it] * (RSTRIDE * 2)
                               + cp_seg[it] * 16;
            CP_ASYNC16(dst, src);
        }
        CP_COMMIT();
    };

    float acc[4][8][4] = {};    // [mi 16-rows][nj 8-cols][frag]

    issue_load(0);
    const int NCHUNK = DIM / KCHUNK;
    for (int c = 0; c < NCHUNK; ++c) {
        if (c + 1 < NCHUNK) { issue_load(c + 1); CP_WAIT(1); }
        else                { CP_WAIT(0); }
        __syncthreads();

        const uint32_t st = sb + (uint32_t)(c & 1) * STAGE_B;
        const uint32_t aH = st, aL = st + TILE_B, bH = st + 2 * TILE_B, bL = st + 3 * TILE_B;

        #pragma unroll
        for (int kk = 0; kk < 2; ++kk) {
            const uint32_t koff = (kk * 16 + lcol8) * 2;
            uint32_t ah[4][4], al[4][4], bh[4][4], bl[4][4];
            #pragma unroll
            for (int mi = 0; mi < 4; ++mi) {
                const uint32_t ro = (wm * 64 + mi * 16 + lrow) * (RSTRIDE * 2) + koff;
                ldsm4(ah[mi], aH + ro);
                ldsm4(al[mi], aL + ro);
            }
            #pragma unroll
            for (int nq = 0; nq < 4; ++nq) {
                const uint32_t ro = (wn * 64 + nq * 16 + lrow) * (RSTRIDE * 2) + koff;
                ldsm4(bh[nq], bH + ro);
                ldsm4(bl[nq], bL + ro);
            }
            // pass 1: Ah x Bh
            #pragma unroll
            for (int mi = 0; mi < 4; ++mi)
                #pragma unroll
                for (int nq = 0; nq < 4; ++nq) {
                    mma16816(acc[mi][nq * 2 + 0], ah[mi], bh[nq][0], bh[nq][2]);
                    mma16816(acc[mi][nq * 2 + 1], ah[mi], bh[nq][1], bh[nq][3]);
                }
            // pass 2: Ah x Bl
            #pragma unroll
            for (int mi = 0; mi < 4; ++mi)
                #pragma unroll
                for (int nq = 0; nq < 4; ++nq) {
                    mma16816(acc[mi][nq * 2 + 0], ah[mi], bl[nq][0], bl[nq][2]);
                    mma16816(acc[mi][nq * 2 + 1], ah[mi], bl[nq][1], bl[nq][3]);
                }
            // pass 3: Al x Bh
            #pragma unroll
            for (int mi = 0; mi < 4; ++mi)
                #pragma unroll
                for (int nq = 0; nq < 4; ++nq) {
                    mma16816(acc[mi][nq * 2 + 0], al[mi], bh[nq][0], bh[nq][2]);
                    mma16816(acc[mi][nq * 2 + 1], al[mi], bh[nq][1], bh[nq][3]);
                }
        }
        __syncthreads();
    }

    #pragma unroll
    for (int mi = 0; mi < 4; ++mi)
        #pragma unroll
        for (int nj = 0; nj < 8; ++nj) {
            const int row = bm * 128 + wm * 64 + mi * 16 + gid;
            const int n = bn * 128 + wn * 64 + nj * 8 + tig * 2;
            if (MODE == 0) {
                const int which = n >> 10;
                const int h = (n >> 6) & (NUM_H - 1);
                const int cc = n & (HD - 1);
                __nv_bfloat16* dh = (which == 0) ? &gQh[h][0][0]
                                  : (which == 1) ? &gKh[h][0][0] : &gVh[h][0][0];
                __nv_bfloat16* dl = (which == 0) ? &gQl[h][0][0]
                                  : (which == 1) ? &gKl[h][0][0] : &gVl[h][0][0];
                const float s = (which == 0) ? 0.125f : 1.0f;
                uint32_t hi, lo;
                split2(acc[mi][nj][0] * s, acc[mi][nj][1] * s, hi, lo);
                *(uint32_t*)&dh[(size_t)row * HD + cc] = hi;
                *(uint32_t*)&dl[(size_t)row * HD + cc] = lo;
                split2(acc[mi][nj][2] * s, acc[mi][nj][3] * s, hi, lo);
                *(uint32_t*)&dh[(size_t)(row + 8) * HD + cc] = hi;
                *(uint32_t*)&dl[(size_t)(row + 8) * HD + cc] = lo;
            } else {
                *(float2*)&C[(size_t)row * N + n] =
                    make_float2(acc[mi][nj][0], acc[mi][nj][1]);
                *(float2*)&C[(size_t)(row + 8) * N + n] =
                    make_float2(acc[mi][nj][2], acc[mi][nj][3]);
            }
        }
}

// ---------------- flash attention, bf16 mma 3-split (unchanged) ------------
#define BR 128
#define BC 64
#define FSTR 72                                // smem row stride in halves
#define Q_TILE_H  (BR * FSTR)                  // 9216 halves
#define KV_TILE_H (BC * FSTR)                  // 4608 halves
#define STAGE_H   (4 * KV_TILE_H)              // 18432 halves
#define FLASH_SMEM_B ((2 * Q_TILE_H + 2 * STAGE_H) * 2)   // 110592 B

__global__ __launch_bounds__(256)
void flash_mma_kernel()
{
    extern __shared__ char fsm[];
    const uint32_t sb = smem_u32(fsm);
    const int tid = threadIdx.x;
    const int qb = blockIdx.x, h = blockIdx.y;
    const int w = tid >> 5, lane = tid & 31;
    const int gid = lane >> 2, tig = lane & 3;
    const int l15 = lane & 15, l16 = lane >> 4;

    // one-time Q load (Qh | Ql), own commit group
    #pragma unroll
    for (int it = 0; it < 8; ++it) {
        int idx = it * 256 + tid;
        int tile = idx >> 10, r = (idx >> 3) & 127, ch = idx & 7;
        const __nv_bfloat16* src = tile == 0 ? &gQh[h][qb * BR + r][ch * 8]
                                             : &gQl[h][qb * BR + r][ch * 8];
        CP_ASYNC16(sb + (tile * Q_TILE_H + r * FSTR + ch * 8) * 2, src);
    }
    CP_COMMIT();

    auto load_kv = [&](int kb) {
        const uint32_t st = sb + (2 * Q_TILE_H + (uint32_t)(kb & 1) * STAGE_H) * 2;
        #pragma unroll
        for (int it = 0; it < 8; ++it) {
            int idx = it * 256 + tid;
            int tile = idx >> 9, r = (idx >> 3) & 63, ch = idx & 7;
            const int tg = kb * BC + r;
            const __nv_bfloat16* src =
                (tile == 0) ? &gKh[h][tg][ch * 8] :
                (tile == 1) ? &gKl[h][tg][ch * 8] :
                (tile == 2) ? &gVh[h][tg][ch * 8] : &gVl[h][tg][ch * 8];
            CP_ASYNC16(st + (tile * KV_TILE_H + r * FSTR + ch * 8) * 2, src);
        }
        CP_COMMIT();
    };

    float o[8][4] = {};
    float m0 = -1e30f, m1 = -1e30f, l0 = 0.f, l1 = 0.f;

    load_kv(0);
    const int NKB = SEQ_T / BC;                 // 32
    for (int kb = 0; kb < NKB; ++kb) {
        if (kb + 1 < NKB) { load_kv(kb + 1); CP_WAIT(1); }
        else              { CP_WAIT(0); }
        __syncthreads();

        const uint32_t qh_b = sb, ql_b = sb + Q_TILE_H * 2;
        const uint32_t st = sb + (2 * Q_TILE_H + (uint32_t)(kb & 1) * STAGE_H) * 2;
        const uint32_t kh_b = st;
        const uint32_t kl_b = st + KV_TILE_H * 2;
        const uint32_t vh_b = st + 2 * KV_TILE_H * 2;
        const uint32_t vl_b = st + 3 * KV_TILE_H * 2;

        // ---- S = Q K^T (3-split, pass-reordered) ----
        float s[8][4] = {};
        #pragma unroll
        for (int ks = 0; ks < 4; ++ks) {
            const uint32_t qoff = ((w * 16 + l15) * FSTR + ks * 16 + l16 * 8) * 2;
            uint32_t qh[4], ql[4];
            ldsm4(qh, qh_b + qoff);
            ldsm4(ql, ql_b + qoff);
            uint32_t kh[4][4], kl[4][4];
            #pragma unroll
            for (int kg = 0; kg < 4; ++kg) {
                const uint32_t koff = ((kg * 16 + l15) * FSTR + ks * 16 + l16 * 8) * 2;
                ldsm4(kh[kg], kh_b + koff);
                ldsm4(kl[kg], kl_b + koff);
            }
            // pass 1: Qh x Kh
            #pragma unroll
            for (int kg = 0; kg < 4; ++kg) {
                mma16816(s[2 * kg],     qh, kh[kg][0], kh[kg][2]);
                mma16816(s[2 * kg + 1], qh, kh[kg][1], kh[kg][3]);
            }
            // pass 2: Qh x Kl
            #pragma unroll
            for (int kg = 0; kg < 4; ++kg) {
                mma16816(s[2 * kg],     qh, kl[kg][0], kl[kg][2]);
                mma16816(s[2 * kg + 1], qh, kl[kg][1], kl[kg][3]);
            }
            // pass 3: Ql x Kh
            #pragma unroll
            for (int kg = 0; kg < 4; ++kg) {
                mma16816(s[2 * kg],     ql, kh[kg][0], kh[kg][2]);
                mma16816(s[2 * kg + 1], ql, kh[kg][1], kh[kg][3]);
            }
        }

        // ---- online softmax (rows gid and gid+8 of this warp) ----
        float mx0 = -1e30f, mx1 = -1e30f;
        #pragma unroll
        for (int nf = 0; nf < 8; ++nf) {
            mx0 = fmaxf(mx0, fmaxf(s[nf][0], s[nf][1]));
            mx1 = fmaxf(mx1, fmaxf(s[nf][2], s[nf][3]));
        }
        mx0 = fmaxf(mx0, __shfl_xor_sync(0xffffffffu, mx0, 1));
        mx0 = fmaxf(mx0, __shfl_xor_sync(0xffffffffu, mx0, 2));
        mx1 = fmaxf(mx1, __shfl_xor_sync(0xffffffffu, mx1, 1));
        mx1 = fmaxf(mx1, __shfl_xor_sync(0xffffffffu, mx1, 2));
        const float mn0 = fmaxf(m0, mx0), mn1 = fmaxf(m1, mx1);
        const float c0 = __expf(m0 - mn0), c1 = __expf(m1 - mn1);
        m0 = mn0; m1 = mn1;
        float sum0 = 0.f, sum1 = 0.f;
        #pragma unroll
        for (int nf = 0; nf < 8; ++nf) {
            s[nf][0] = __expf(s[nf][0] - mn0);
            s[nf][1] = __expf(s[nf][1] - mn0);
            s[nf][2] = __expf(s[nf][2] - mn1);
            s[nf][3] = __expf(s[nf][3] - mn1);
            sum0 += s[nf][0] + s[nf][1];
            sum1 += s[nf][2] + s[nf][3];
        }
        sum0 += __shfl_xor_sync(0xffffffffu, sum0, 1);
        sum0 += __shfl_xor_sync(0xffffffffu, sum0, 2);
        sum1 += __shfl_xor_sync(0xffffffffu, sum1, 1);
        sum1 += __shfl_xor_sync(0xffffffffu, sum1, 2);
        l0 = l0 * c0 + sum0;
        l1 = l1 * c1 + sum1;
        #pragma unroll
        for (int nf = 0; nf < 8; ++nf) {
            o[nf][0] *= c0; o[nf][1] *= c0;
            o[nf][2] *= c1; o[nf][3] *= c1;
        }

        // ---- O += P V (3-split, pass-reordered; V via ldmatrix.trans) ----
        #pragma unroll
        for (int ks = 0; ks < 4; ++ks) {
            uint32_t ph[4], pl[4];
            split2(s[2 * ks][0],     s[2 * ks][1],     ph[0], pl[0]);
            split2(s[2 * ks][2],     s[2 * ks][3],     ph[1], pl[1]);
            split2(s[2 * ks + 1][0], s[2 * ks + 1][1], ph[2], pl[2]);
            split2(s[2 * ks + 1][2], s[2 * ks + 1][3], ph[3], pl[3]);
            uint32_t vh[4][4], vl[4][4];
            #pragma unroll
            for (int hg = 0; hg < 4; ++hg) {
                const uint32_t voff = ((ks * 16 + l15) * FSTR + hg * 16 + l16 * 8) * 2;
                ldsm4t(vh[hg], vh_b + voff);
                ldsm4t(vl[hg], vl_b + voff);
            }
            // pass 1: Ph x Vh
            #pragma unroll
            for (int hg = 0; hg < 4; ++hg) {
                mma16816(o[2 * hg],     ph, vh[hg][0], vh[hg][1]);
                mma16816(o[2 * hg + 1], ph, vh[hg][2], vh[hg][3]);
            }
            // pass 2: Ph x Vl
            #pragma unroll
            for (int hg = 0; hg < 4; ++hg) {
                mma16816(o[2 * hg],     ph, vl[hg][0], vl[hg][1]);
                mma16816(o[2 * hg + 1], ph, vl[hg][2], vl[hg][3]);
            }
            // pass 3: Pl x Vh
            #pragma unroll
            for (int hg = 0; hg < 4; ++hg) {
                mma16816(o[2 * hg],     pl, vh[hg][0], vh[hg][1]);
                mma16816(o[2 * hg + 1], pl, vh[hg][2], vh[hg][3]);
            }
        }
        __syncthreads();
    }

    // ---- epilogue: y = O / l, split to gY hi/lo ----
    const float i0 = 1.0f / l0, i1 = 1.0f / l1;
    const int t0 = qb * BR + w * 16 + gid;
    #pragma unroll
    for (int nf = 0; nf < 8; ++nf) {
        const int col = h * 64 + nf * 8 + 2 * tig;
        uint32_t hi, lo;
        split2(o[nf][0] * i0, o[nf][1] * i0, hi, lo);
        *(uint32_t*)&gY_hi[t0][col] = hi;
        *(uint32_t*)&gY_lo[t0][col] = lo;
        split2(o[nf][2] * i1, o[nf][3] * i1, hi, lo);
        *(uint32_t*)&gY_hi[t0 + 8][col] = hi;
        *(uint32_t*)&gY_lo[t0 + 8][col] = lo;
    }
}

// ---------------- launch ---------------------------------------------------
extern "C" void kernel_launch(void* const* d_in, const int* in_sizes, int n_in,
                              void* d_out, int out_size)
{
    (void)in_sizes; (void)n_in; (void)out_size;
    const float* x     = (const float*)d_in[0];
    const float* Wqkv  = (const float*)d_in[1];
    const float* Wproj = (const float*)d_in[2];
    float* out = (float*)d_out;

    cudaFuncSetAttribute(mma_gemm_kernel<0>, cudaFuncAttributeMaxDynamicSharedMemorySize,
                         GEMM_SMEM);
    cudaFuncSetAttribute(mma_gemm_kernel<1>, cudaFuncAttributeMaxDynamicSharedMemorySize,
                         GEMM_SMEM);
    cudaFuncSetAttribute(flash_mma_kernel, cudaFuncAttributeMaxDynamicSharedMemorySize,
                         FLASH_SMEM_B);

    conv_split_kernel<<<SEQ_T * DIM / 4 / 256, 256>>>(x);
    transpose_split_kernel<0><<<dim3(3 * DIM / 32, DIM / 32), dim3(32, 8)>>>(Wqkv);
    transpose_split_kernel<1><<<dim3(DIM / 32, DIM / 32), dim3(32, 8)>>>(Wproj);

    // QKV = x @ W_qkv, split-scattered into gQ/gK/gV
    mma_gemm_kernel<0><<<dim3(3 * DIM / 128, SEQ_T / 128), 128, GEMM_SMEM>>>(
        nullptr, 3 * DIM);

    // fused attention -> gY hi/lo
    flash_mma_kernel<<<dim3(SEQ_T / BR, NUM_H), 256, FLASH_SMEM_B>>>();

    // out = y @ W_proj
    mma_gemm_kernel<1><<<dim3(DIM / 128, SEQ_T / 128), 128, GEMM_SMEM>>>(
        out, DIM);
}